// round 1
// baseline (speedup 1.0000x reference)
#include <cuda_runtime.h>

#define NN 8192

typedef unsigned long long ull;

// ---------------------------------------------------------------------------
// f32x2 packed helpers (sm_103a): ptxas will not auto-fuse FFMA2 from C++.
// ---------------------------------------------------------------------------
__device__ __forceinline__ ull pack_dup(float x) {
    ull r;
    asm("mov.b64 %0, {%1, %2};" : "=l"(r) : "f"(x), "f"(x));
    return r;
}
__device__ __forceinline__ void unpack2f(ull v, float& x, float& y) {
    asm("mov.b64 {%0, %1}, %2;" : "=f"(x), "=f"(y) : "l"(v));
}
__device__ __forceinline__ void fma2(ull& d, ull a, ull b) {
    asm("fma.rn.f32x2 %0, %1, %2, %0;" : "+l"(d) : "l"(a), "l"(b));
}

// ---------------------------------------------------------------------------
// Scratch (no cudaMalloc allowed): G buffer and split-K partials.
// ---------------------------------------------------------------------------
__device__ float g_buf_dev[NN * 64];                 // current G = H @ W^T
__device__ float part_buf_dev[8 * NN * 64];          // [KSPLIT][NN][D]

// ---------------------------------------------------------------------------
// Big GEMM: P[ks] = A[:, kchunk] @ G[kchunk, :]   (split-K partials)
//   BM=256 rows per CTA, BK=32, 256 threads, TM=8, TN=4/8, f32x2 accumulators
//   reads g_buf_dev, writes part_buf_dev
// ---------------------------------------------------------------------------
template<int D, int KSPLIT, int TN>
__global__ void __launch_bounds__(256, 2)
big_gemm(const float* __restrict__ A) {
    constexpr int BK    = 32;
    constexpr int TM    = 8;
    constexpr int THR_N = D / TN;          // 8
    constexpr int THR_M = 256 / THR_N;     // 32
    constexpr int BM    = THR_M * TM;      // 256
    constexpr int KCH   = NN / KSPLIT;     // 1024
    static_assert(THR_N * THR_M == 256, "bad thread tiling");

    __shared__ float As[BK][BM + 1];       // transposed [k][m], +1 pad for STS banks
    __shared__ float Gs[BK][D];

    const float* __restrict__ G = g_buf_dev;
    float* __restrict__ P = part_buf_dev;

    const int tid  = threadIdx.x;
    const int tx   = tid % THR_N;
    const int ty   = tid / THR_N;
    const int row0 = blockIdx.x * BM;
    const int kbeg = blockIdx.y * KCH;

    // A loader: 32 rows per pass, 8 float4 per row
    const int a_m = tid / 8;               // 0..31
    const int a_k = (tid % 8) * 4;         // 0,4,...,28

    // G loader
    constexpr int GF4 = D / 4;
    const int g_k0 = tid / GF4;
    const int g_c  = (tid % GF4) * 4;
    constexpr int G_PASS_ROWS = 256 / GF4;

    ull acc[TM][TN / 2];
    #pragma unroll
    for (int i = 0; i < TM; ++i)
        #pragma unroll
        for (int j = 0; j < TN / 2; ++j)
            acc[i][j] = 0ull;              // bits == {0.f, 0.f}

    for (int kt = 0; kt < KCH; kt += BK) {
        // --- load A tile (coalesced float4, transposed scalar STS, pad-1 banks)
        #pragma unroll
        for (int p = 0; p < BM / 32; ++p) {
            const int m = p * 32 + a_m;
            float4 v = *(const float4*)(A + (size_t)(row0 + m) * NN + (kbeg + kt + a_k));
            As[a_k + 0][m] = v.x;
            As[a_k + 1][m] = v.y;
            As[a_k + 2][m] = v.z;
            As[a_k + 3][m] = v.w;
        }
        // --- load G tile (row-major float4)
        #pragma unroll
        for (int p = 0; p < BK / G_PASS_ROWS; ++p) {
            const int gk = p * G_PASS_ROWS + g_k0;
            *(float4*)&Gs[gk][g_c] =
                *(const float4*)(G + (size_t)(kbeg + kt + gk) * D + g_c);
        }
        __syncthreads();

        #pragma unroll 8
        for (int kk = 0; kk < BK; ++kk) {
            // a: 8 scalar LDS (4 distinct banks across ty, broadcast across tx)
            ull ad[TM];
            #pragma unroll
            for (int i = 0; i < TM; ++i)
                ad[i] = pack_dup(As[kk][ty * TM + i]);
            // g: pairs straight from smem as ulonglong2 (16B aligned)
            ull g2[TN / 2];
            const ulonglong2* gp = (const ulonglong2*)&Gs[kk][tx * TN];
            #pragma unroll
            for (int j = 0; j < TN / 4; ++j) {
                ulonglong2 t = gp[j];
                g2[2 * j]     = t.x;
                g2[2 * j + 1] = t.y;
            }
            #pragma unroll
            for (int i = 0; i < TM; ++i)
                #pragma unroll
                for (int j = 0; j < TN / 2; ++j)
                    fma2(acc[i][j], ad[i], g2[j]);
        }
        __syncthreads();
    }

    // epilogue: partial slice [blockIdx.y][row][col]
    float* Pb = P + (size_t)blockIdx.y * NN * D;
    #pragma unroll
    for (int i = 0; i < TM; ++i) {
        const int r = row0 + ty * TM + i;
        #pragma unroll
        for (int j4 = 0; j4 < TN / 4; ++j4) {
            float4 v;
            unpack2f(acc[i][2 * j4],     v.x, v.y);
            unpack2f(acc[i][2 * j4 + 1], v.z, v.w);
            *(float4*)(Pb + (size_t)r * D + tx * TN + j4 * 4) = v;
        }
    }
}

// ---------------------------------------------------------------------------
// Row-wise fused kernel: h = [relu](sum of KSPLIT partials) ; G' = h @ W^T
//   one thread per row; W broadcast from smem. Writes g_buf_dev.
//   FROM_PART=false reads the xsrc pointer (used for the first layer: X @ W1^T)
// ---------------------------------------------------------------------------
template<int DIN, int DOUT, int KSPLIT, bool RELU, bool FROM_PART>
__global__ void __launch_bounds__(256)
row_gemm(const float* __restrict__ xsrc, const float* __restrict__ W) {
    __shared__ float Ws[DOUT * DIN];
    for (int i = threadIdx.x; i < DOUT * DIN; i += 256)
        Ws[i] = W[i];
    __syncthreads();

    const float* __restrict__ src = FROM_PART ? part_buf_dev : xsrc;
    const int r = blockIdx.x * 256 + threadIdx.x;

    float h[DIN];
    #pragma unroll
    for (int i4 = 0; i4 < DIN / 4; ++i4) {
        float4 v = *(const float4*)(src + (size_t)r * DIN + i4 * 4);
        h[4 * i4 + 0] = v.x; h[4 * i4 + 1] = v.y;
        h[4 * i4 + 2] = v.z; h[4 * i4 + 3] = v.w;
    }
    #pragma unroll
    for (int s = 1; s < KSPLIT; ++s) {
        #pragma unroll
        for (int i4 = 0; i4 < DIN / 4; ++i4) {
            float4 v = *(const float4*)(src + ((size_t)s * NN + r) * DIN + i4 * 4);
            h[4 * i4 + 0] += v.x; h[4 * i4 + 1] += v.y;
            h[4 * i4 + 2] += v.z; h[4 * i4 + 3] += v.w;
        }
    }
    if (RELU) {
        #pragma unroll
        for (int i = 0; i < DIN; ++i)
            h[i] = fmaxf(h[i], 0.0f);
    }

    float* __restrict__ out = g_buf_dev;
    for (int j4 = 0; j4 < DOUT / 4; ++j4) {
        float4 o;
        #pragma unroll
        for (int jj = 0; jj < 4; ++jj) {
            float a = 0.0f;
            const float* w = &Ws[(j4 * 4 + jj) * DIN];
            #pragma unroll
            for (int i = 0; i < DIN; ++i)
                a = fmaf(h[i], w[i], a);
            ((float*)&o)[jj] = a;
        }
        *(float4*)(out + (size_t)r * DOUT + j4 * 4) = o;
    }
}

// ---------------------------------------------------------------------------
// Final reduce: out = sum of KSPLIT partials (no relu, no W)
// ---------------------------------------------------------------------------
template<int D, int KSPLIT>
__global__ void __launch_bounds__(256)
reduce_out(float* __restrict__ out) {
    const int idx = blockIdx.x * 256 + threadIdx.x;   // float4 index
    const float4* p4 = (const float4*)part_buf_dev;
    float4 acc = p4[idx];
    #pragma unroll
    for (int s = 1; s < KSPLIT; ++s) {
        float4 v = p4[(size_t)s * (NN * D / 4) + idx];
        acc.x += v.x; acc.y += v.y; acc.z += v.z; acc.w += v.w;
    }
    ((float4*)out)[idx] = acc;
}

// ---------------------------------------------------------------------------
// Launch: G1 = X@W1^T ; for each layer: P = A@G (split-K) ; fuse reduce+relu+W
// ---------------------------------------------------------------------------
extern "C" void kernel_launch(void* const* d_in, const int* in_sizes, int n_in,
                              void* d_out, int out_size) {
    (void)in_sizes; (void)n_in; (void)out_size;
    const float* A  = (const float*)d_in[0];
    const float* X  = (const float*)d_in[1];
    const float* W1 = (const float*)d_in[2];
    const float* W2 = (const float*)d_in[3];
    const float* W3 = (const float*)d_in[4];
    const float* W4 = (const float*)d_in[5];
    float* out = (float*)d_out;

    const dim3 big_grid(NN / 256, 8);

    // Layer 1: G1 = X @ W1^T ; H1 = relu(A @ G1)
    row_gemm<32, 32, 1, false, false><<<NN / 256, 256>>>(X, W1);
    big_gemm<32, 8, 4><<<big_grid, 256>>>(A);
    // Layer 2: G2 = H1 @ W2^T ; H2 = relu(A @ G2)
    row_gemm<32, 64, 8, true, true><<<NN / 256, 256>>>(nullptr, W2);
    big_gemm<64, 8, 8><<<big_grid, 256>>>(A);
    // Layer 3: G3 = H2 @ W3^T ; H3 = relu(A @ G3)
    row_gemm<64, 64, 8, true, true><<<NN / 256, 256>>>(nullptr, W3);
    big_gemm<64, 8, 8><<<big_grid, 256>>>(A);
    // Layer 4: G4 = H3 @ W4^T ; out = A @ G4 (no relu)
    row_gemm<64, 32, 8, true, true><<<NN / 256, 256>>>(nullptr, W4);
    big_gemm<32, 8, 4><<<big_grid, 256>>>(A);
    reduce_out<32, 8><<<NN * 32 / 4 / 256, 256>>>(out);
}

// round 3
// speedup vs baseline: 1.8909x; 1.8909x over previous
#include <cuda_runtime.h>
#include <cuda_bf16.h>
#include <cstdint>

#define NN 8192
#define KSPLIT 4
#define KCH (NN / KSPLIT)          // 2048
#define NTILES (KCH / 32)          // 64 k-tiles of BK=32

// ---------------------------------------------------------------------------
// Scratch (no cudaMalloc allowed)
// ---------------------------------------------------------------------------
__device__ __nv_bfloat16 gt_hi_dev[64 * NN];      // G^T hi  [D][NN]
__device__ __nv_bfloat16 gt_lo_dev[64 * NN];      // G^T lo
__device__ float part_buf_dev[KSPLIT * NN * 64];  // split-K partials

// ---------------------------------------------------------------------------
// PTX helpers (plain sm_103-legal: mma.sync / ldmatrix / cp.async only)
// ---------------------------------------------------------------------------
__device__ __forceinline__ uint32_t smem_u32(const void* p) {
    uint32_t a;
    asm("{ .reg .u64 t; cvta.to.shared.u64 t, %1; cvt.u32.u64 %0, t; }"
        : "=r"(a) : "l"(p));
    return a;
}
__device__ __forceinline__ void cp16(uint32_t dst, const void* src) {
    asm volatile("cp.async.cg.shared.global [%0], [%1], 16;\n"
                 :: "r"(dst), "l"(src));
}
#define CP_COMMIT() asm volatile("cp.async.commit_group;" ::: "memory")
#define CP_WAIT0()  asm volatile("cp.async.wait_group 0;" ::: "memory")

__device__ __forceinline__ void ldm4(uint32_t* a, uint32_t addr) {
    asm volatile("ldmatrix.sync.aligned.m8n8.x4.shared.b16 {%0,%1,%2,%3}, [%4];"
                 : "=r"(a[0]), "=r"(a[1]), "=r"(a[2]), "=r"(a[3]) : "r"(addr));
}
__device__ __forceinline__ void mma_bf16(float* c, const uint32_t* a,
                                         uint32_t b0, uint32_t b1) {
    asm volatile(
        "mma.sync.aligned.m16n8k16.row.col.f32.bf16.bf16.f32 "
        "{%0,%1,%2,%3},{%4,%5,%6,%7},{%8,%9},{%0,%1,%2,%3};"
        : "+f"(c[0]), "+f"(c[1]), "+f"(c[2]), "+f"(c[3])
        : "r"(a[0]), "r"(a[1]), "r"(a[2]), "r"(a[3]), "r"(b0), "r"(b1));
}
// pack two fp32 -> bf16x2 (lo elem in low half)
__device__ __forceinline__ uint32_t pack_bf2(float lo, float hi) {
    uint32_t r;
    asm("cvt.rn.bf16x2.f32 %0, %1, %2;" : "=r"(r) : "f"(hi), "f"(lo));
    return r;
}

// ---------------------------------------------------------------------------
// Big GEMM: part[ks] = A[:, kchunk] (fp32, split in-kernel) @ G[kchunk, :]
//   BM=128, BK=32, 8 warps (warp = 16 rows), 2-stage pipeline.
//   Smem rows padded to 80B (stride 40 bf16): conflict-free ldmatrix + LDS.
// ---------------------------------------------------------------------------
template<int D>
__global__ void __launch_bounds__(256, 2)
big_mma(const float* __restrict__ A) {
    constexpr int NT  = D / 8;            // n-tiles per warp
    constexpr int ASZ = 128 * 80;         // bytes per A plane (10240)
    constexpr int GSZ = D * 80;           // bytes per G plane
    constexpr int STG = 2 * ASZ + 2 * GSZ;  // per stage

    extern __shared__ char smem[];
    const uint32_t sb = smem_u32(smem);
    const int tid  = threadIdx.x;
    const int wid  = tid >> 5;
    const int lane = tid & 31;
    const size_t row0 = (size_t)blockIdx.x * 128;
    const size_t k0   = (size_t)blockIdx.y * KCH;

    // A loader geometry: 32 rows/pass, 8 float4 per row, 4 passes
    const int ar = tid >> 3;              // 0..31
    const int ac = (tid & 7) * 4;         // fp32 col within BK
    // G loader geometry: 4 x 16B segments per 64B row
    const int gr = tid >> 2;              // row (n)
    const int gs = (tid & 3) * 8;         // bf16 elems offset

    float4 Af[4];

    auto ldA = [&](int kt) {
        const float* p = A + (row0 + ar) * NN + k0 + (size_t)kt * 32 + ac;
        #pragma unroll
        for (int i = 0; i < 4; ++i)
            Af[i] = *(const float4*)(p + (size_t)32 * i * NN);
    };
    auto stA = [&](int s) {
        const uint32_t bo = (uint32_t)(s * STG) + (uint32_t)(ar * 80 + (tid & 7) * 8);
        #pragma unroll
        for (int i = 0; i < 4; ++i) {
            const float4 v = Af[i];
            uint32_t h01 = pack_bf2(v.x, v.y);
            uint32_t h23 = pack_bf2(v.z, v.w);
            float l0 = v.x - __uint_as_float(h01 << 16);
            float l1 = v.y - __uint_as_float(h01 & 0xFFFF0000u);
            float l2 = v.z - __uint_as_float(h23 << 16);
            float l3 = v.w - __uint_as_float(h23 & 0xFFFF0000u);
            uint32_t lo01 = pack_bf2(l0, l1);
            uint32_t lo23 = pack_bf2(l2, l3);
            const uint32_t off = bo + (uint32_t)(i * 32 * 80);
            *(uint2*)(smem + off)        = make_uint2(h01, h23);
            *(uint2*)(smem + off + ASZ)  = make_uint2(lo01, lo23);
        }
    };
    auto ldG = [&](int s, int kt) {
        if (D == 64 || tid < 128) {
            const uint32_t dst = sb + s * STG + 2 * ASZ + gr * 80 + gs * 2;
            const size_t   go  = (size_t)gr * NN + k0 + (size_t)kt * 32 + gs;
            cp16(dst,       gt_hi_dev + go);
            cp16(dst + GSZ, gt_lo_dev + go);
        }
    };

    float acc[NT][4];
    #pragma unroll
    for (int j = 0; j < NT; ++j)
        #pragma unroll
        for (int q = 0; q < 4; ++q) acc[j][q] = 0.0f;

    // prologue: fill stage 0
    ldA(0);
    ldG(0, 0);
    CP_COMMIT();
    stA(0);
    CP_WAIT0();
    __syncthreads();

    for (int kt = 0; kt < NTILES; ++kt) {
        const int s = kt & 1;
        const bool more = (kt + 1 < NTILES);
        if (more) {
            ldA(kt + 1);
            ldG(s ^ 1, kt + 1);
            CP_COMMIT();
        }

        // ---- compute on stage s
        const uint32_t base = sb + s * STG;
        const uint32_t abyte = base + (uint32_t)((wid * 16 + (lane & 15)) * 80
                                                 + (lane >> 4) * 16);
        const uint32_t gbase = (uint32_t)(s * STG + 2 * ASZ
                                          + (lane >> 2) * 80 + (lane & 3) * 4);
        #pragma unroll
        for (int kk = 0; kk < 2; ++kk) {
            uint32_t Ah[4], Al[4];
            ldm4(Ah, abyte + kk * 32);
            ldm4(Al, abyte + kk * 32 + ASZ);
            #pragma unroll
            for (int j = 0; j < NT; ++j) {
                const uint32_t go = gbase + kk * 32 + j * 8 * 80;
                uint32_t bh0 = *(const uint32_t*)(smem + go);
                uint32_t bh1 = *(const uint32_t*)(smem + go + 16);
                uint32_t bl0 = *(const uint32_t*)(smem + go + GSZ);
                uint32_t bl1 = *(const uint32_t*)(smem + go + GSZ + 16);
                mma_bf16(acc[j], Ah, bh0, bh1);
                mma_bf16(acc[j], Ah, bl0, bl1);
                mma_bf16(acc[j], Al, bh0, bh1);
            }
        }

        if (more) stA(s ^ 1);
        CP_WAIT0();
        __syncthreads();
    }

    // epilogue: thread t holds rows (lane/4, lane/4+8), cols 2*(lane%4)+{0,1}
    float* P = part_buf_dev + ((size_t)blockIdx.y * NN + row0 + wid * 16) * D;
    const int r0 = lane >> 2;
    const int c0 = (lane & 3) * 2;
    #pragma unroll
    for (int j = 0; j < NT; ++j) {
        *(float2*)&P[(size_t)r0 * D + j * 8 + c0]       = make_float2(acc[j][0], acc[j][1]);
        *(float2*)&P[(size_t)(r0 + 8) * D + j * 8 + c0] = make_float2(acc[j][2], acc[j][3]);
    }
}

// ---------------------------------------------------------------------------
// Row-wise: h = [relu](sum partials) ; G' = h @ W^T, stored as G'^T bf16 hi/lo
// ---------------------------------------------------------------------------
template<int DIN, int DOUT, int KS, bool RELU, bool FROM_PART>
__global__ void __launch_bounds__(256)
row_gemm(const float* __restrict__ xsrc, const float* __restrict__ W) {
    __shared__ float Ws[DOUT * DIN];
    for (int i = threadIdx.x; i < DOUT * DIN; i += 256) Ws[i] = W[i];
    __syncthreads();

    const float* __restrict__ src = FROM_PART ? part_buf_dev : xsrc;
    const int r = blockIdx.x * 256 + threadIdx.x;

    float h[DIN];
    #pragma unroll
    for (int i4 = 0; i4 < DIN / 4; ++i4) {
        float4 v = *(const float4*)(src + (size_t)r * DIN + i4 * 4);
        h[4 * i4 + 0] = v.x; h[4 * i4 + 1] = v.y;
        h[4 * i4 + 2] = v.z; h[4 * i4 + 3] = v.w;
    }
    #pragma unroll
    for (int s = 1; s < KS; ++s)
        #pragma unroll
        for (int i4 = 0; i4 < DIN / 4; ++i4) {
            float4 v = *(const float4*)(src + ((size_t)s * NN + r) * DIN + i4 * 4);
            h[4 * i4 + 0] += v.x; h[4 * i4 + 1] += v.y;
            h[4 * i4 + 2] += v.z; h[4 * i4 + 3] += v.w;
        }
    if (RELU) {
        #pragma unroll
        for (int i = 0; i < DIN; ++i) h[i] = fmaxf(h[i], 0.0f);
    }

    #pragma unroll
    for (int j = 0; j < DOUT; ++j) {
        float a = 0.0f;
        const float* w = &Ws[j * DIN];
        #pragma unroll
        for (int i = 0; i < DIN; ++i) a = fmaf(h[i], w[i], a);
        __nv_bfloat16 hi = __float2bfloat16_rn(a);
        __nv_bfloat16 lo = __float2bfloat16_rn(a - __bfloat162float(hi));
        gt_hi_dev[(size_t)j * NN + r] = hi;
        gt_lo_dev[(size_t)j * NN + r] = lo;
    }
}

// ---------------------------------------------------------------------------
// Final reduce: out = sum of KSPLIT partials
// ---------------------------------------------------------------------------
__global__ void __launch_bounds__(256)
reduce_out(float* __restrict__ out) {
    const int idx = blockIdx.x * 256 + threadIdx.x;   // float4 index
    const float4* p4 = (const float4*)part_buf_dev;
    float4 a = p4[idx];
    #pragma unroll
    for (int s = 1; s < KSPLIT; ++s) {
        float4 b = p4[(size_t)s * (NN * 32 / 4) + idx];
        a.x += b.x; a.y += b.y; a.z += b.z; a.w += b.w;
    }
    ((float4*)out)[idx] = a;
}

// ---------------------------------------------------------------------------
// Launch
// ---------------------------------------------------------------------------
extern "C" void kernel_launch(void* const* d_in, const int* in_sizes, int n_in,
                              void* d_out, int out_size) {
    (void)in_sizes; (void)n_in; (void)out_size;
    const float* A  = (const float*)d_in[0];
    const float* X  = (const float*)d_in[1];
    const float* W1 = (const float*)d_in[2];
    const float* W2 = (const float*)d_in[3];
    const float* W3 = (const float*)d_in[4];
    const float* W4 = (const float*)d_in[5];
    float* out = (float*)d_out;

    constexpr int SMEM32 = 2 * (2 * 128 * 80 + 2 * 32 * 80);  // 51200
    constexpr int SMEM64 = 2 * (2 * 128 * 80 + 2 * 64 * 80);  // 61440
    cudaFuncSetAttribute(big_mma<32>, cudaFuncAttributeMaxDynamicSharedMemorySize, SMEM32);
    cudaFuncSetAttribute(big_mma<64>, cudaFuncAttributeMaxDynamicSharedMemorySize, SMEM64);

    const dim3 big_grid(NN / 128, KSPLIT);

    // Layer 1: G1 = X @ W1^T ; P = A @ G1
    row_gemm<32, 32, 1, false, false><<<NN / 256, 256>>>(X, W1);
    big_mma<32><<<big_grid, 256, SMEM32>>>(A);
    // Layer 2
    row_gemm<32, 64, KSPLIT, true, true><<<NN / 256, 256>>>(nullptr, W2);
    big_mma<64><<<big_grid, 256, SMEM64>>>(A);
    // Layer 3
    row_gemm<64, 64, KSPLIT, true, true><<<NN / 256, 256>>>(nullptr, W3);
    big_mma<64><<<big_grid, 256, SMEM64>>>(A);
    // Layer 4 (no relu on output)
    row_gemm<64, 32, KSPLIT, true, true><<<NN / 256, 256>>>(nullptr, W4);
    big_mma<32><<<big_grid, 256, SMEM32>>>(A);
    reduce_out<<<NN * 32 / 4 / 256, 256>>>(out);
}

// round 4
// speedup vs baseline: 1.9828x; 1.0486x over previous
#include <cuda_runtime.h>
#include <cuda_bf16.h>
#include <cstdint>

#define NN 8192
#define KSPLIT 4
#define KCH (NN / KSPLIT)          // 2048
#define NTILES (KCH / 32)          // 64 k-tiles of BK=32

// ---------------------------------------------------------------------------
// Scratch (no cudaMalloc allowed)
// ---------------------------------------------------------------------------
__device__ __nv_bfloat16 gt_hi_dev[64 * NN];      // G^T hi  [D][NN]
__device__ __nv_bfloat16 gt_lo_dev[64 * NN];      // G^T lo
__device__ float part_buf_dev[KSPLIT * NN * 64];  // split-K partials

// ---------------------------------------------------------------------------
// PTX helpers (plain sm_103-legal: mma.sync / ldmatrix / cp.async only)
// ---------------------------------------------------------------------------
__device__ __forceinline__ uint32_t smem_u32(const void* p) {
    uint32_t a;
    asm("{ .reg .u64 t; cvta.to.shared.u64 t, %1; cvt.u32.u64 %0, t; }"
        : "=r"(a) : "l"(p));
    return a;
}
__device__ __forceinline__ void cp16(uint32_t dst, const void* src) {
    asm volatile("cp.async.cg.shared.global [%0], [%1], 16;\n"
                 :: "r"(dst), "l"(src));
}
#define CP_COMMIT() asm volatile("cp.async.commit_group;" ::: "memory")
#define CP_WAIT0()  asm volatile("cp.async.wait_group 0;" ::: "memory")
#define CP_WAIT1()  asm volatile("cp.async.wait_group 1;" ::: "memory")

__device__ __forceinline__ void ldm4(uint32_t* a, uint32_t addr) {
    asm volatile("ldmatrix.sync.aligned.m8n8.x4.shared.b16 {%0,%1,%2,%3}, [%4];"
                 : "=r"(a[0]), "=r"(a[1]), "=r"(a[2]), "=r"(a[3]) : "r"(addr));
}
__device__ __forceinline__ void mma_bf16(float* c, uint32_t a0, uint32_t a1,
                                         uint32_t a2, uint32_t a3,
                                         uint32_t b0, uint32_t b1) {
    asm volatile(
        "mma.sync.aligned.m16n8k16.row.col.f32.bf16.bf16.f32 "
        "{%0,%1,%2,%3},{%4,%5,%6,%7},{%8,%9},{%0,%1,%2,%3};"
        : "+f"(c[0]), "+f"(c[1]), "+f"(c[2]), "+f"(c[3])
        : "r"(a0), "r"(a1), "r"(a2), "r"(a3), "r"(b0), "r"(b1));
}
// pack two fp32 -> bf16x2 (x in low half)
__device__ __forceinline__ uint32_t pack_bf2(float lo, float hi) {
    uint32_t r;
    asm("cvt.rn.bf16x2.f32 %0, %1, %2;" : "=r"(r) : "f"(hi), "f"(lo));
    return r;
}

// ---------------------------------------------------------------------------
// Big GEMM: part[ks] = A[:, kchunk] (fp32, split in-kernel) @ G[kchunk, :]
//   BM=128, BK=32. 8 warps as 4 row-groups x 2 col-groups; warp tile 32 x D/2.
//   A: LDG fp32 -> cvt bf16 hi/lo -> smem (2 stages, 80B row stride).
//   G: cp.async bf16 hi/lo (3 stages, prefetch distance 2, wait_group 1).
//   All operand fetch in the MMA loop via ldmatrix.x4 (conflict-free @80B).
// ---------------------------------------------------------------------------
template<int D>
__global__ void __launch_bounds__(256, 2)
big_mma(const float* __restrict__ A) {
    constexpr int NJ   = D / 16;            // n-tiles (of 8) per warp
    constexpr int NHLF = D / 2;             // cols per col-group
    constexpr int GSZ  = D * 80;            // one G plane (hi or lo)
    constexpr int APL  = 128 * 80;          // one A plane = 10240 B
    constexpr int AREA = 4 * APL;           // 2 stages x hi/lo

    extern __shared__ char smem[];
    const uint32_t sb = smem_u32(smem);
    const int tid  = threadIdx.x;
    const int wid  = tid >> 5;
    const int lane = tid & 31;
    const int rw   = wid >> 1;              // row group 0..3
    const int cw   = wid & 1;               // col group 0..1
    const size_t row0 = (size_t)blockIdx.x * 128;
    const size_t k0   = (size_t)blockIdx.y * KCH;

    // A loader geometry: 32 rows/pass, 8 float4 per row, 4 passes
    const int ar = tid >> 3;                // 0..31
    const int ac = (tid & 7) * 4;           // fp32 col within BK
    // G loader geometry: 4 x 16B segments per 64B row
    const int gr = tid >> 2;
    const int gs = (tid & 3) * 8;

    float4 Af[4];
    auto ldA = [&](int kt) {
        const float* p = A + (row0 + ar) * NN + k0 + (size_t)kt * 32 + ac;
        #pragma unroll
        for (int i = 0; i < 4; ++i)
            Af[i] = *(const float4*)(p + (size_t)32 * i * NN);
    };
    auto stA = [&](int s) {
        const uint32_t bo = (uint32_t)(s * 2 * APL + ar * 80 + (tid & 7) * 8);
        #pragma unroll
        for (int i = 0; i < 4; ++i) {
            const float4 v = Af[i];
            uint32_t h01 = pack_bf2(v.x, v.y);
            uint32_t h23 = pack_bf2(v.z, v.w);
            float l0 = v.x - __uint_as_float(h01 << 16);
            float l1 = v.y - __uint_as_float(h01 & 0xFFFF0000u);
            float l2 = v.z - __uint_as_float(h23 << 16);
            float l3 = v.w - __uint_as_float(h23 & 0xFFFF0000u);
            uint32_t lo01 = pack_bf2(l0, l1);
            uint32_t lo23 = pack_bf2(l2, l3);
            const uint32_t off = bo + (uint32_t)(i * 32 * 80);
            *(uint2*)(smem + off)       = make_uint2(h01, h23);
            *(uint2*)(smem + off + APL) = make_uint2(lo01, lo23);
        }
    };
    auto ldG = [&](int g, int kt) {
        if (D == 64 || tid < 128) {
            const uint32_t dst = sb + AREA + (uint32_t)(g * 2 * GSZ + gr * 80 + gs * 2);
            const size_t   go  = (size_t)gr * NN + k0 + (size_t)kt * 32 + gs;
            cp16(dst,       gt_hi_dev + go);
            cp16(dst + GSZ, gt_lo_dev + go);
        }
    };

    float acc[2][NJ][4];
    #pragma unroll
    for (int mb = 0; mb < 2; ++mb)
        #pragma unroll
        for (int j = 0; j < NJ; ++j)
            #pragma unroll
            for (int q = 0; q < 4; ++q) acc[mb][j][q] = 0.0f;

    // prologue: G two tiles ahead, A one tile ahead (in smem stage 0)
    ldG(0, 0); CP_COMMIT();
    ldG(1, 1); CP_COMMIT();
    ldA(0);
    stA(0);

    // ldmatrix lane addressing (conflict-free with 80B row stride)
    const uint32_t a_lane = (uint32_t)((lane & 15) * 80 + (lane >> 4) * 16);
    const uint32_t g_lane = (uint32_t)((lane & 7) * 80 + (lane >> 3) * 16);

    for (int kt = 0; kt < NTILES; ++kt) {
        if (kt == NTILES - 1) CP_WAIT0(); else CP_WAIT1();
        __syncthreads();                    // G(kt) + A(kt) visible to all

        if (kt + 2 < NTILES) { ldG((kt + 2) % 3, kt + 2); CP_COMMIT(); }
        if (kt + 1 < NTILES) ldA(kt + 1);

        const int sa = kt & 1;
        const int sg = kt % 3;

        // A fragments: 2 m16 blocks x 2 kk x hi/lo
        const uint32_t ab = sb + (uint32_t)(sa * 2 * APL + rw * 32 * 80) + a_lane;
        uint32_t Ah[2][2][4], Al[2][2][4];   // [mb][kk][reg]
        #pragma unroll
        for (int mb = 0; mb < 2; ++mb)
            #pragma unroll
            for (int kk = 0; kk < 2; ++kk) {
                ldm4(Ah[mb][kk], ab + mb * 16 * 80 + kk * 32);
                ldm4(Al[mb][kk], ab + mb * 16 * 80 + kk * 32 + APL);
            }

        const uint32_t gb = sb + AREA + (uint32_t)(sg * 2 * GSZ + cw * NHLF * 80) + g_lane;
        #pragma unroll
        for (int j = 0; j < NJ; ++j) {
            uint32_t bh[4], bl[4];           // x4 covers kk0 (b0,b1) + kk1 (b0,b1)
            ldm4(bh, gb + j * 8 * 80);
            ldm4(bl, gb + j * 8 * 80 + GSZ);
            #pragma unroll
            for (int mb = 0; mb < 2; ++mb) {
                float* c = acc[mb][j];
                mma_bf16(c, Ah[mb][0][0], Ah[mb][0][1], Ah[mb][0][2], Ah[mb][0][3], bh[0], bh[1]);
                mma_bf16(c, Ah[mb][1][0], Ah[mb][1][1], Ah[mb][1][2], Ah[mb][1][3], bh[2], bh[3]);
                mma_bf16(c, Ah[mb][0][0], Ah[mb][0][1], Ah[mb][0][2], Ah[mb][0][3], bl[0], bl[1]);
                mma_bf16(c, Ah[mb][1][0], Ah[mb][1][1], Ah[mb][1][2], Ah[mb][1][3], bl[2], bl[3]);
                mma_bf16(c, Al[mb][0][0], Al[mb][0][1], Al[mb][0][2], Al[mb][0][3], bh[0], bh[1]);
                mma_bf16(c, Al[mb][1][0], Al[mb][1][1], Al[mb][1][2], Al[mb][1][3], bh[2], bh[3]);
            }
        }

        if (kt + 1 < NTILES) stA(sa ^ 1);   // protected by next iter's barrier
    }

    // epilogue: warp rows rw*32 + mb*16 + lane/4 + {0,8}; cols cw*NHLF + j*8 + 2*(lane&3)
    float* P = part_buf_dev + ((size_t)blockIdx.y * NN + row0 + rw * 32) * D + cw * NHLF;
    const int r0 = lane >> 2;
    const int c0 = (lane & 3) * 2;
    #pragma unroll
    for (int mb = 0; mb < 2; ++mb)
        #pragma unroll
        for (int j = 0; j < NJ; ++j) {
            float* c = acc[mb][j];
            *(float2*)&P[(size_t)(mb * 16 + r0) * D + j * 8 + c0]     = make_float2(c[0], c[1]);
            *(float2*)&P[(size_t)(mb * 16 + r0 + 8) * D + j * 8 + c0] = make_float2(c[2], c[3]);
        }
}

// ---------------------------------------------------------------------------
// Row-wise: h = [relu](sum partials) ; G' = h @ W^T, stored as G'^T bf16 hi/lo
// ---------------------------------------------------------------------------
template<int DIN, int DOUT, int KS, bool RELU, bool FROM_PART>
__global__ void __launch_bounds__(256)
row_gemm(const float* __restrict__ xsrc, const float* __restrict__ W) {
    __shared__ float Ws[DOUT * DIN];
    for (int i = threadIdx.x; i < DOUT * DIN; i += 256) Ws[i] = W[i];
    __syncthreads();

    const float* __restrict__ src = FROM_PART ? part_buf_dev : xsrc;
    const int r = blockIdx.x * 256 + threadIdx.x;

    float h[DIN];
    #pragma unroll
    for (int i4 = 0; i4 < DIN / 4; ++i4) {
        float4 v = *(const float4*)(src + (size_t)r * DIN + i4 * 4);
        h[4 * i4 + 0] = v.x; h[4 * i4 + 1] = v.y;
        h[4 * i4 + 2] = v.z; h[4 * i4 + 3] = v.w;
    }
    #pragma unroll
    for (int s = 1; s < KS; ++s)
        #pragma unroll
        for (int i4 = 0; i4 < DIN / 4; ++i4) {
            float4 v = *(const float4*)(src + ((size_t)s * NN + r) * DIN + i4 * 4);
            h[4 * i4 + 0] += v.x; h[4 * i4 + 1] += v.y;
            h[4 * i4 + 2] += v.z; h[4 * i4 + 3] += v.w;
        }
    if (RELU) {
        #pragma unroll
        for (int i = 0; i < DIN; ++i) h[i] = fmaxf(h[i], 0.0f);
    }

    #pragma unroll
    for (int j = 0; j < DOUT; ++j) {
        float a = 0.0f;
        const float* w = &Ws[j * DIN];
        #pragma unroll
        for (int i = 0; i < DIN; ++i) a = fmaf(h[i], w[i], a);
        __nv_bfloat16 hi = __float2bfloat16_rn(a);
        __nv_bfloat16 lo = __float2bfloat16_rn(a - __bfloat162float(hi));
        gt_hi_dev[(size_t)j * NN + r] = hi;
        gt_lo_dev[(size_t)j * NN + r] = lo;
    }
}

// ---------------------------------------------------------------------------
// Final reduce: out = sum of KSPLIT partials
// ---------------------------------------------------------------------------
__global__ void __launch_bounds__(256)
reduce_out(float* __restrict__ out) {
    const int idx = blockIdx.x * 256 + threadIdx.x;   // float4 index
    const float4* p4 = (const float4*)part_buf_dev;
    float4 a = p4[idx];
    #pragma unroll
    for (int s = 1; s < KSPLIT; ++s) {
        float4 b = p4[(size_t)s * (NN * 32 / 4) + idx];
        a.x += b.x; a.y += b.y; a.z += b.z; a.w += b.w;
    }
    ((float4*)out)[idx] = a;
}

// ---------------------------------------------------------------------------
// Launch
// ---------------------------------------------------------------------------
extern "C" void kernel_launch(void* const* d_in, const int* in_sizes, int n_in,
                              void* d_out, int out_size) {
    (void)in_sizes; (void)n_in; (void)out_size;
    const float* A  = (const float*)d_in[0];
    const float* X  = (const float*)d_in[1];
    const float* W1 = (const float*)d_in[2];
    const float* W2 = (const float*)d_in[3];
    const float* W3 = (const float*)d_in[4];
    const float* W4 = (const float*)d_in[5];
    float* out = (float*)d_out;

    constexpr int SMEM32 = 4 * 128 * 80 + 3 * 2 * 32 * 80;   // 56320
    constexpr int SMEM64 = 4 * 128 * 80 + 3 * 2 * 64 * 80;   // 71680
    cudaFuncSetAttribute(big_mma<32>, cudaFuncAttributeMaxDynamicSharedMemorySize, SMEM32);
    cudaFuncSetAttribute(big_mma<64>, cudaFuncAttributeMaxDynamicSharedMemorySize, SMEM64);

    const dim3 big_grid(NN / 128, KSPLIT);

    // Layer 1: G1 = X @ W1^T ; P = A @ G1
    row_gemm<32, 32, 1, false, false><<<NN / 256, 256>>>(X, W1);
    big_mma<32><<<big_grid, 256, SMEM32>>>(A);
    // Layer 2
    row_gemm<32, 64, KSPLIT, true, true><<<NN / 256, 256>>>(nullptr, W2);
    big_mma<64><<<big_grid, 256, SMEM64>>>(A);
    // Layer 3
    row_gemm<64, 64, KSPLIT, true, true><<<NN / 256, 256>>>(nullptr, W3);
    big_mma<64><<<big_grid, 256, SMEM64>>>(A);
    // Layer 4 (no relu on output)
    row_gemm<64, 32, KSPLIT, true, true><<<NN / 256, 256>>>(nullptr, W4);
    big_mma<32><<<big_grid, 256, SMEM32>>>(A);
    reduce_out<<<NN * 32 / 4 / 256, 256>>>(out);
}